// round 8
// baseline (speedup 1.0000x reference)
#include <cuda_runtime.h>
#include <cuda_fp16.h>
#include <cstdint>

#define BATCH    8192
#define HID      128
#define GATES    512
#define LOOKBACK 48
#define HORIZON  12
#define TSTEPS   60
#define DIN      8
#define STATE    (BATCH*HID)
#define KROW0    160          // 8 x + 24 zero pad + 128 h (halves)
#define KROW1    256          // 128 h0 + 128 h1prev
#define NTHR     512
#define MTILE    64

// ---- device globals (no allocation allowed) ----
__device__ __half g_WB0[GATES*KROW0];   // n-major [n][k], n = unit*4+gate
__device__ __half g_WB1[GATES*KROW1];
__device__ float  g_b0 [GATES];
__device__ float  g_b1 [GATES];
__device__ __half g_h0 [2*STATE];
__device__ __half g_h1 [2*STATE];
__device__ float  g_c0 [STATE];
__device__ float  g_c1 [STATE];
__device__ float  g_pred[BATCH];

// ---- smem map (bytes) ----
// bias0 512f @0 | bias1 512f @2048 | wfc 128f @4096
// A0: 64 x 168 halves (stride 336B)  @4608   (21504)
// A1: 64 x 264 halves (stride 528B)  @26112  (33792)   cols 0..127 = h0 (filled by L0 epi)
// BW: 16 warps x 2 bufs x (32 x 40 halves = 2560B)     @59904  (81920)
// HB: 64 x 136 halves (stride 272B)  @141824 (17408)   h1 for fc + writeback
// CB0: 64 x 132 f32 (stride 528B)    @159232 (33792)
// CB1: 64 x 132 f32                  @193024 (33792)
#define OB0   0
#define OB1   2048
#define OWFC  4096
#define OA0   4608
#define OA1   26112
#define OBW   59904
#define OHB   141824
#define OCB0  159232
#define OCB1  193024
#define SMEM_TOTAL 226816

// ---------------- helpers ----------------
__device__ __forceinline__ uint32_t smem_u32(const void* p){
    uint32_t a;
    asm("{ .reg .u64 t; cvta.to.shared.u64 t, %1; cvt.u32.u64 %0, t; }" : "=r"(a) : "l"(p));
    return a;
}
__device__ __forceinline__ void cpa16(uint32_t dst, const void* src){
    asm volatile("cp.async.cg.shared.global [%0], [%1], 16;" :: "r"(dst), "l"(src));
}
#define CP_COMMIT() asm volatile("cp.async.commit_group;" ::: "memory")
__device__ __forceinline__ void mma16(float* d, const uint32_t* a, const uint32_t* b){
    asm volatile("mma.sync.aligned.m16n8k16.row.col.f32.f16.f16.f32 "
        "{%0,%1,%2,%3}, {%4,%5,%6,%7}, {%8,%9}, {%0,%1,%2,%3};"
        : "+f"(d[0]), "+f"(d[1]), "+f"(d[2]), "+f"(d[3])
        : "r"(a[0]), "r"(a[1]), "r"(a[2]), "r"(a[3]), "r"(b[0]), "r"(b[1]));
}
__device__ __forceinline__ float sigm_f(float x){
    x = fminf(fmaxf(x, -30.f), 30.f);
    return __fdividef(1.f, 1.f + __expf(-x));
}
__device__ __forceinline__ float tanh_f(float x){
    x = fminf(fmaxf(x, -15.f), 15.f);
    float e = __expf(2.f*x);
    return 1.f - __fdividef(2.f, e + 1.f);
}

// ---------------- weight repack (n-major fp16) + state zero ----------------
__global__ void prep_kernel(const float* __restrict__ Wih0, const float* __restrict__ Whh0,
                            const float* __restrict__ bih0, const float* __restrict__ bhh0,
                            const float* __restrict__ Wih1, const float* __restrict__ Whh1,
                            const float* __restrict__ bih1, const float* __restrict__ bhh1)
{
    const int NW0 = GATES*KROW0, NW1 = GATES*KROW1;
    const int total = NW0 + NW1 + 2*GATES + 4*STATE;
    for (int idx = blockIdx.x*blockDim.x + threadIdx.x; idx < total;
         idx += gridDim.x*blockDim.x) {
        int i = idx;
        if (i < NW0) { int n = i/KROW0, k = i%KROW0; int row = (n&3)*HID + (n>>2);
            float v = 0.f;
            if (k < DIN)       v = Wih0[row*DIN + k];
            else if (k >= 32)  v = Whh0[row*HID + (k-32)];
            g_WB0[i] = __float2half_rn(v); continue; }
        i -= NW0;
        if (i < NW1) { int n = i>>8, k = i&255; int row = (n&3)*HID + (n>>2);
            float v = (k < HID) ? Wih1[row*HID + k] : Whh1[row*HID + (k-HID)];
            g_WB1[i] = __float2half_rn(v); continue; }
        i -= NW1;
        if (i < GATES) { int row = (i&3)*HID + (i>>2); g_b0[i] = bih0[row]+bhh0[row]; continue; }
        i -= GATES;
        if (i < GATES) { int row = (i&3)*HID + (i>>2); g_b1[i] = bih1[row]+bhh1[row]; continue; }
        i -= GATES;
        if (i < STATE) { g_h0[i] = __ushort_as_half((unsigned short)0); continue; }
        i -= STATE;
        if (i < STATE) { g_h1[i] = __ushort_as_half((unsigned short)0); continue; }
        i -= STATE;
        if (i < STATE) { g_c0[i] = 0.f; continue; }
        i -= STATE;
        g_c1[i] = 0.f;
    }
}

// ---------------- fused timestep: L0 + L1 + fc, M=64 x N=512 per CTA ----------------
// 16 warps, each owns 32 n-cols for ALL 64 rows; warp-private B double-buffer.
__global__ __launch_bounds__(NTHR, 1) void lstm_step(
    const float* __restrict__ inputs,
    const float* __restrict__ Wfc, const float* __restrict__ bfc,
    float* __restrict__ out, int t)
{
    extern __shared__ __align__(16) char smem[];
    const int tid = threadIdx.x, lane = tid & 31, wid = tid >> 5;
    const int m0 = blockIdx.x * MTILE;
    const int g = lane >> 2, tq = lane & 3;
    const uint32_t sb = smem_u32(smem);
    const int rp = t & 1, wp = rp ^ 1;
    const bool use_bg = (t > LOOKBACK);
    const __half* h0r = g_h0 + rp*STATE;
    __half*       h0w = g_h0 + wp*STATE;
    const __half* h1r = g_h1 + rp*STATE;
    __half*       h1w = g_h1 + wp*STATE;

    float*  bs0  = (float*)(smem + OB0);
    float*  bs1  = (float*)(smem + OB1);
    float*  wfcs = (float*)(smem + OWFC);
    __half* HB   = (__half*)(smem + OHB);
    float*  CB0  = (float*)(smem + OCB0);
    float*  CB1  = (float*)(smem + OCB1);

    // ---- stage: biases, wfc, A0(h0prev), A1(h1prev), CB0(c0), CB1(c1), x ----
    bs0[tid] = g_b0[tid];
    bs1[tid] = g_b1[tid];
    if (tid < HID) wfcs[tid] = Wfc[tid];
    #pragma unroll
    for (int i = 0; i < 2; i++){ int idx = tid + i*NTHR, row = idx>>4, q = idx&15;
        cpa16(sb + OA0 + row*336 + 64 + q*16,
              (const char*)(h0r + (size_t)(m0+row)*HID) + q*16); }
    #pragma unroll
    for (int i = 0; i < 2; i++){ int idx = tid + i*NTHR, row = idx>>4, q = idx&15;
        cpa16(sb + OA1 + row*528 + 256 + q*16,
              (const char*)(h1r + (size_t)(m0+row)*HID) + q*16); }
    #pragma unroll
    for (int i = 0; i < 4; i++){ int idx = tid + i*NTHR, row = idx>>5, q = idx&31;
        cpa16(sb + OCB0 + row*528 + q*16,
              (const char*)(g_c0 + (size_t)(m0+row)*HID) + q*16); }
    #pragma unroll
    for (int i = 0; i < 4; i++){ int idx = tid + i*NTHR, row = idx>>5, q = idx&31;
        cpa16(sb + OCB1 + row*528 + q*16,
              (const char*)(g_c1 + (size_t)(m0+row)*HID) + q*16); }
    {   // x cols (f32->f16 + BG) + zero pad into A0 chunk 0
        __half* A0h = (__half*)(smem + OA0);
        int m = tid >> 3, p = tid & 7;
        __half hv[4];
        #pragma unroll
        for (int c = 0; c < 4; c++){
            int k = p*4 + c; float v = 0.f;
            if (k < DIN)
                v = (use_bg && k == 0) ? g_pred[m0+m]
                                       : inputs[(size_t)(m0+m)*(TSTEPS*DIN) + t*DIN + k];
            hv[c] = __float2half_rn(v);
        }
        *(uint2*)&A0h[m*168 + p*4] = *(uint2*)hv;
    }
    CP_COMMIT();

    const uint32_t wb = sb + OBW + wid*5120;
    auto issueB = [&](const __half* WBp, int Krow, int j, int b){
        uint32_t dst = wb + (uint32_t)b*2560;
        #pragma unroll
        for (int i = 0; i < 4; i++){
            int row = (lane>>2) + i*8, q = lane & 3;
            cpa16(dst + (uint32_t)(row*80 + q*16),
                  (const char*)WBp + ((size_t)(wid*32 + row)*Krow + j*32)*2 + q*16);
        }
        CP_COMMIT();
    };

    float acc[4][4][4];
    auto zacc = [&]{
        #pragma unroll
        for (int a = 0; a < 4; a++)
            #pragma unroll
            for (int b = 0; b < 4; b++)
                #pragma unroll
                for (int d = 0; d < 4; d++) acc[a][b][d] = 0.f;
    };
    auto gemm = [&](const uint32_t* Aw, int ast, int j, int b){
        const uint32_t* Bp = (const uint32_t*)(smem + OBW + wid*5120 + b*2560);
        #pragma unroll
        for (int s = 0; s < 2; s++){
            uint32_t af[4][4];
            #pragma unroll
            for (int mi = 0; mi < 4; mi++){
                int r0 = mi*16 + g;
                af[mi][0] = Aw[ r0   *ast + j*16 + s*8 + tq];
                af[mi][1] = Aw[(r0+8)*ast + j*16 + s*8 + tq];
                af[mi][2] = Aw[ r0   *ast + j*16 + s*8 + tq + 4];
                af[mi][3] = Aw[(r0+8)*ast + j*16 + s*8 + tq + 4];
            }
            uint32_t bf[4][2];
            #pragma unroll
            for (int nj = 0; nj < 4; nj++){
                int nn = nj*8 + g;
                bf[nj][0] = Bp[nn*20 + s*8 + tq];
                bf[nj][1] = Bp[nn*20 + s*8 + tq + 4];
            }
            #pragma unroll
            for (int mi = 0; mi < 4; mi++)
                #pragma unroll
                for (int nj = 0; nj < 4; nj++)
                    mma16(acc[mi][nj], af[mi], bf[nj]);
        }
    };
    auto epi = [&](const float* bsm, float* CB, __half* hdst, int hst){
        #pragma unroll
        for (int mi = 0; mi < 4; mi++)
            #pragma unroll
            for (int nj = 0; nj < 4; nj++){
                int nl = wid*32 + nj*8 + 2*tq;
                float v0 = acc[mi][nj][0] + bsm[nl];
                float v1 = acc[mi][nj][1] + bsm[nl+1];
                float v2 = acc[mi][nj][2] + bsm[nl];
                float v3 = acc[mi][nj][3] + bsm[nl+1];
                float p0 = __shfl_xor_sync(0xffffffffu, v0, 1);
                float p1 = __shfl_xor_sync(0xffffffffu, v1, 1);
                float p2 = __shfl_xor_sync(0xffffffffu, v2, 1);
                float p3 = __shfl_xor_sync(0xffffffffu, v3, 1);
                if (!(lane & 1)){                 // even lanes: (i,f); partner: (g,o)
                    int u = nl >> 2, ml = mi*16 + g;
                    {
                        float cold = CB[ml*132 + u];
                        float cn = sigm_f(v1)*cold + sigm_f(v0)*tanh_f(p0);
                        CB[ml*132 + u] = cn;
                        hdst[ml*hst + u] = __float2half_rn(sigm_f(p1)*tanh_f(cn));
                    }
                    {
                        float cold = CB[(ml+8)*132 + u];
                        float cn = sigm_f(v3)*cold + sigm_f(v2)*tanh_f(p2);
                        CB[(ml+8)*132 + u] = cn;
                        hdst[(ml+8)*hst + u] = __float2half_rn(sigm_f(p3)*tanh_f(cn));
                    }
                }
            }
    };

    // ---- layer 0: K=160, 5 chunks ----
    zacc();
    issueB(g_WB0, KROW0, 0, 0);
    issueB(g_WB0, KROW0, 1, 1);
    asm volatile("cp.async.wait_group 2;" ::: "memory");   // staging group done
    __syncthreads();
    const uint32_t* A0w = (const uint32_t*)(smem + OA0);
    #pragma unroll
    for (int j = 0; j < 5; j++){
        if (j < 4) asm volatile("cp.async.wait_group 1;" ::: "memory");
        else       asm volatile("cp.async.wait_group 0;" ::: "memory");
        __syncwarp();
        gemm(A0w, 84, j, j & 1);
        __syncwarp();
        if (j + 2 < 5) issueB(g_WB0, KROW0, j + 2, j & 1);
    }
    // prefetch L1 weight chunks during the L0 epilogue
    issueB(g_WB1, KROW1, 0, 0);
    issueB(g_WB1, KROW1, 1, 1);

    // ---- L0 epilogue: gates -> c0 (smem), h0 -> A1 cols 0..127 ----
    epi(bs0, CB0, (__half*)(smem + OA1), 264);
    __syncthreads();
    // coalesced writebacks: c0, h0(next step)
    #pragma unroll
    for (int i = 0; i < 4; i++){ int idx = tid + i*NTHR, row = idx>>5, q = idx&31;
        float4 v = *(float4*)(smem + OCB0 + row*528 + q*16);
        *(float4*)&g_c0[(size_t)(m0+row)*HID + q*4] = v; }
    #pragma unroll
    for (int i = 0; i < 2; i++){ int idx = tid + i*NTHR, row = idx>>4, q = idx&15;
        uint4 w = *(uint4*)(smem + OA1 + row*528 + q*16);
        *(uint4*)&h0w[(size_t)(m0+row)*HID + q*8] = w; }

    // ---- layer 1: K=256, 8 chunks ----
    zacc();
    const uint32_t* A1w = (const uint32_t*)(smem + OA1);
    #pragma unroll
    for (int j = 0; j < 8; j++){
        if (j < 7) asm volatile("cp.async.wait_group 1;" ::: "memory");
        else       asm volatile("cp.async.wait_group 0;" ::: "memory");
        __syncwarp();
        gemm(A1w, 132, j, j & 1);
        __syncwarp();
        if (j + 2 < 8) issueB(g_WB1, KROW1, j + 2, j & 1);
    }

    // ---- L1 epilogue: gates -> c1, h1 -> HB ----
    epi(bs1, CB1, HB, 136);
    __syncthreads();
    #pragma unroll
    for (int i = 0; i < 4; i++){ int idx = tid + i*NTHR, row = idx>>5, q = idx&31;
        float4 v = *(float4*)(smem + OCB1 + row*528 + q*16);
        *(float4*)&g_c1[(size_t)(m0+row)*HID + q*4] = v; }
    #pragma unroll
    for (int i = 0; i < 2; i++){ int idx = tid + i*NTHR, row = idx>>4, q = idx&15;
        uint4 w = *(uint4*)(smem + OHB + row*272 + q*16);
        *(uint4*)&h1w[(size_t)(m0+row)*HID + q*8] = w; }

    // ---- fc head (in-kernel): 8 lanes per row ----
    if (t >= LOOKBACK){
        int row = tid >> 3, sub = tid & 7;
        float s = 0.f;
        #pragma unroll
        for (int jj = 0; jj < 16; jj++){
            int u = sub + 8*jj;
            s += __half2float(HB[row*136 + u]) * wfcs[u];
        }
        s += __shfl_xor_sync(0xffffffffu, s, 4);
        s += __shfl_xor_sync(0xffffffffu, s, 2);
        s += __shfl_xor_sync(0xffffffffu, s, 1);
        if (sub == 0){
            float p = s + bfc[0];
            out[(size_t)(m0+row)*HORIZON + (t - LOOKBACK)] = p;
            g_pred[m0+row] = p;
        }
    }
}

// ---------------- launch ----------------
extern "C" void kernel_launch(void* const* d_in, const int* in_sizes, int n_in,
                              void* d_out, int out_size)
{
    const float* inputs = (const float*)d_in[0];
    const float* Wih0 = (const float*)d_in[1];
    const float* Whh0 = (const float*)d_in[2];
    const float* bih0 = (const float*)d_in[3];
    const float* bhh0 = (const float*)d_in[4];
    const float* Wih1 = (const float*)d_in[5];
    const float* Whh1 = (const float*)d_in[6];
    const float* bih1 = (const float*)d_in[7];
    const float* bhh1 = (const float*)d_in[8];
    const float* Wfc  = (const float*)d_in[9];
    const float* bfc  = (const float*)d_in[10];
    float* out = (float*)d_out;

    cudaFuncSetAttribute(lstm_step, cudaFuncAttributeMaxDynamicSharedMemorySize, SMEM_TOTAL);

    prep_kernel<<<2048, 256>>>(Wih0, Whh0, bih0, bhh0, Wih1, Whh1, bih1, bhh1);

    for (int t = 0; t < TSTEPS; t++)
        lstm_step<<<BATCH/MTILE, NTHR, SMEM_TOTAL>>>(inputs, Wfc, bfc, out, t);
}

// round 9
// speedup vs baseline: 1.6915x; 1.6915x over previous
#include <cuda_runtime.h>
#include <cuda_fp16.h>
#include <cstdint>

#define BATCH    8192
#define HID      128
#define GATES    512
#define LOOKBACK 48
#define HORIZON  12
#define TSTEPS   60
#define DIN      8
#define STATE    (BATCH*HID)
#define KROW0    160          // 8 x-cols + 24 zero pad + 128 h-cols (halves)
#define KROW1    256
#define NTHR     512

// ---- device globals (no allocation allowed) ----
__device__ __half g_WB0[GATES*KROW0];   // n-major [n][k], n = unit*4+gate
__device__ __half g_WB1[GATES*KROW1];
__device__ float  g_b0 [GATES];
__device__ float  g_b1 [GATES];
__device__ __half g_h0 [2*STATE];
__device__ __half g_h1 [2*STATE];
__device__ float  g_c0 [STATE];
__device__ float  g_c1 [STATE];
__device__ float  g_fcp[2*BATCH];       // fc partials per n-slice

// ---- smem layout (bytes) ----
#define SM_A(b)   (2048 + (b)*10240)
#define SM_B(b)   (22528 + (b)*20480)
#define SM_CB     2048
#define SM_HB     35328
#define SMEM_TOTAL 63488

// ---------------- helpers ----------------
__device__ __forceinline__ uint32_t smem_u32(const void* p){
    uint32_t a;
    asm("{ .reg .u64 t; cvta.to.shared.u64 t, %1; cvt.u32.u64 %0, t; }" : "=r"(a) : "l"(p));
    return a;
}
__device__ __forceinline__ void cpa16(uint32_t dst, const void* src){
    asm volatile("cp.async.cg.shared.global [%0], [%1], 16;" :: "r"(dst), "l"(src));
}
__device__ __forceinline__ void mma16(float* d, const uint32_t* a, const uint32_t* b){
    asm volatile("mma.sync.aligned.m16n8k16.row.col.f32.f16.f16.f32 "
        "{%0,%1,%2,%3}, {%4,%5,%6,%7}, {%8,%9}, {%0,%1,%2,%3};"
        : "+f"(d[0]), "+f"(d[1]), "+f"(d[2]), "+f"(d[3])
        : "r"(a[0]), "r"(a[1]), "r"(a[2]), "r"(a[3]), "r"(b[0]), "r"(b[1]));
}
// fast activations: single MUFU-class op each (tanh.approx), no clamps/divides
__device__ __forceinline__ float tanh_f(float x){
    float y; asm("tanh.approx.f32 %0, %1;" : "=f"(y) : "f"(x));
    return y;
}
__device__ __forceinline__ float sigm_f(float x){
    float y; asm("tanh.approx.f32 %0, %1;" : "=f"(y) : "f"(0.5f*x));
    return fmaf(0.5f, y, 0.5f);
}

// ---------------- weight repack (n-major fp16) + state zero ----------------
__global__ void prep_kernel(const float* __restrict__ Wih0, const float* __restrict__ Whh0,
                            const float* __restrict__ bih0, const float* __restrict__ bhh0,
                            const float* __restrict__ Wih1, const float* __restrict__ Whh1,
                            const float* __restrict__ bih1, const float* __restrict__ bhh1)
{
    const int NW0 = GATES*KROW0, NW1 = GATES*KROW1;
    const int total = NW0 + NW1 + 2*GATES + 4*STATE;
    for (int idx = blockIdx.x*blockDim.x + threadIdx.x; idx < total;
         idx += gridDim.x*blockDim.x) {
        int i = idx;
        if (i < NW0) { int n = i/KROW0, k = i%KROW0; int row = (n&3)*HID + (n>>2);
            float v = 0.f;
            if (k < DIN)       v = Wih0[row*DIN + k];
            else if (k >= 32)  v = Whh0[row*HID + (k-32)];
            g_WB0[i] = __float2half_rn(v); continue; }
        i -= NW0;
        if (i < NW1) { int n = i>>8, k = i&255; int row = (n&3)*HID + (n>>2);
            float v = (k < HID) ? Wih1[row*HID + k] : Whh1[row*HID + (k-HID)];
            g_WB1[i] = __float2half_rn(v); continue; }
        i -= NW1;
        if (i < GATES) { int row = (i&3)*HID + (i>>2); g_b0[i] = bih0[row]+bhh0[row]; continue; }
        i -= GATES;
        if (i < GATES) { int row = (i&3)*HID + (i>>2); g_b1[i] = bih1[row]+bhh1[row]; continue; }
        i -= GATES;
        if (i < STATE) { g_h0[i] = __ushort_as_half((unsigned short)0); continue; }
        i -= STATE;
        if (i < STATE) { g_h1[i] = __ushort_as_half((unsigned short)0); continue; }
        i -= STATE;
        if (i < STATE) { g_c0[i] = 0.f; continue; }
        i -= STATE;
        g_c1[i] = 0.f;
    }
}

// ---------------- fused LSTM cell: fp16 mma.sync, 512 thr, M=128 x N=256 tile ----------------
__global__ __launch_bounds__(NTHR, 1) void lstm_cell(
    const float* __restrict__ xf, int sx,
    const __half* __restrict__ asrc0, const __half* __restrict__ asrc1,
    const __half* __restrict__ WB, int Krow,
    const float* __restrict__ bias,
    float* __restrict__ cglob, __half* __restrict__ hout,
    const float* __restrict__ Wfc, const float* __restrict__ bfc,
    float* __restrict__ fcp, float* __restrict__ out,
    int isl0, int use_bg, int outcol, int dofc)
{
    extern __shared__ __align__(16) char smem[];
    const int tid = threadIdx.x, lane = tid & 31, wid = tid >> 5;
    const int m0 = blockIdx.x * 128, n0 = blockIdx.y * 256, slice = blockIdx.y;
    const int wm0 = (wid >> 3) * 64, wn0 = (wid & 7) * 32;
    const int g = lane >> 2, tq = lane & 3;
    const uint32_t sbase = smem_u32(smem);
    float* bsm  = (float*)smem;
    float* wfcs = (float*)(smem + 1024);
    float* predS= (float*)(smem + 1536);

    if (tid < 256) bsm[tid] = bias[n0 + tid];
    if (tid < 128) wfcs[tid] = Wfc[tid];

    if (use_bg) {
        if (tid < 128) {
            float pv = bfc[0] + fcp[m0 + tid] + fcp[BATCH + m0 + tid];
            predS[tid] = pv;
            if (n0 == 0) out[(size_t)(m0 + tid)*HORIZON + outcol] = pv;
        }
        __syncthreads();
    }

    float acc[4][4][4];
    #pragma unroll
    for (int a = 0; a < 4; a++)
        #pragma unroll
        for (int b = 0; b < 4; b++)
            #pragma unroll
            for (int d = 0; d < 4; d++) acc[a][b][d] = 0.f;

    const int nch = Krow >> 5;

    auto issue = [&](int j){
        const int b = j & 1;
        const uint32_t asb = sbase + SM_A(b);
        const uint32_t bsb = sbase + SM_B(b);
        const char* wsrc = (const char*)WB + ((size_t)n0*Krow + j*32)*2;
        #pragma unroll
        for (int i = 0; i < 2; i++) {              // B: 256 n-rows x 32 k halves
            int idx = tid + i*NTHR;
            int row = idx >> 2, q = idx & 3;
            cpa16(bsb + (uint32_t)(row*80 + q*16), wsrc + (size_t)row*Krow*2 + q*16);
        }
        if (!(isl0 && j == 0)) {                   // A: 128 m-rows x 32 k halves
            const __half* ap; int koff;
            if (isl0)       { ap = asrc0; koff = (j-1)*32; }
            else if (j < 4) { ap = asrc0; koff = j*32; }
            else            { ap = asrc1; koff = (j-4)*32; }
            int row = tid >> 2, q = tid & 3;
            cpa16(asb + (uint32_t)(row*80 + q*16),
                  (const char*)(ap + (size_t)(m0+row)*HID + koff) + q*16);
        }
    };

    if (isl0) {                                    // chunk0: x cols (f32->f16 + BG) + pad
        __half* As0 = (__half*)(smem + SM_A(0));
        int m = tid >> 2, part = tid & 3;
        __half hv[8];
        #pragma unroll
        for (int c = 0; c < 8; c++) {
            int k = part*8 + c;
            float v = 0.f;
            if (k < DIN) v = (use_bg && k == 0) ? predS[m] : xf[(size_t)(m0+m)*sx + k];
            hv[c] = __float2half_rn(v);
        }
        *(uint4*)&As0[m*40 + part*8] = *(uint4*)hv;
    }
    issue(0);
    asm volatile("cp.async.commit_group;" ::: "memory");

    for (int j = 0; j < nch; j++) {
        const int b = j & 1;
        if (j + 1 < nch) {
            issue(j + 1);
            asm volatile("cp.async.commit_group;" ::: "memory");
            asm volatile("cp.async.wait_group 1;" ::: "memory");
        } else {
            asm volatile("cp.async.wait_group 0;" ::: "memory");
        }
        __syncthreads();
        const uint32_t* As = (const uint32_t*)(smem + SM_A(b));  // word stride 20
        const uint32_t* Bs = (const uint32_t*)(smem + SM_B(b));  // word stride 20
        #pragma unroll
        for (int s = 0; s < 2; s++) {
            uint32_t af[4][4];
            #pragma unroll
            for (int mi = 0; mi < 4; mi++) {
                int row0 = wm0 + mi*16 + g;
                af[mi][0] = As[ row0   *20 + s*8 + tq];
                af[mi][1] = As[(row0+8)*20 + s*8 + tq];
                af[mi][2] = As[ row0   *20 + s*8 + tq + 4];
                af[mi][3] = As[(row0+8)*20 + s*8 + tq + 4];
            }
            uint32_t bf[4][2];
            #pragma unroll
            for (int nj = 0; nj < 4; nj++) {
                int nn = wn0 + nj*8 + g;
                bf[nj][0] = Bs[nn*20 + s*8 + tq];
                bf[nj][1] = Bs[nn*20 + s*8 + tq + 4];
            }
            #pragma unroll
            for (int mi = 0; mi < 4; mi++)
                #pragma unroll
                for (int nj = 0; nj < 4; nj++)
                    mma16(acc[mi][nj], af[mi], bf[nj]);
        }
        __syncthreads();
    }

    // -------- epilogue --------
    float*  cbuf = (float*)(smem + SM_CB);    // 128 x 65 f32
    __half* hbuf = (__half*)(smem + SM_HB);   // 128 x 66 half
    const int ub = n0 >> 2;
    #pragma unroll
    for (int i = 0; i < 4; i++) {             // c old: global -> smem, coalesced
        int idx = tid + i*NTHR;
        int m = idx >> 4, q = idx & 15;
        float4 v = *(const float4*)&cglob[(size_t)(m0+m)*HID + ub + q*4];
        cbuf[m*65 + q*4 + 0] = v.x; cbuf[m*65 + q*4 + 1] = v.y;
        cbuf[m*65 + q*4 + 2] = v.z; cbuf[m*65 + q*4 + 3] = v.w;
    }
    __syncthreads();
    #pragma unroll
    for (int mi = 0; mi < 4; mi++) {
        #pragma unroll
        for (int nj = 0; nj < 4; nj++) {
            int nl = wn0 + nj*8 + 2*tq;
            float v0 = acc[mi][nj][0] + bsm[nl];
            float v1 = acc[mi][nj][1] + bsm[nl+1];
            float v2 = acc[mi][nj][2] + bsm[nl];
            float v3 = acc[mi][nj][3] + bsm[nl+1];
            float p0 = __shfl_xor_sync(0xffffffffu, v0, 1);
            float p1 = __shfl_xor_sync(0xffffffffu, v1, 1);
            float p2 = __shfl_xor_sync(0xffffffffu, v2, 1);
            float p3 = __shfl_xor_sync(0xffffffffu, v3, 1);
            if (!(lane & 1)) {                 // even lanes: (i,f); partner: (g,o)
                int u  = nl >> 2;
                int ml = wm0 + mi*16 + g;
                {
                    float cold = cbuf[ml*65 + u];
                    float cn = sigm_f(v1)*cold + sigm_f(v0)*tanh_f(p0);
                    cbuf[ml*65 + u] = cn;
                    hbuf[ml*66 + u] = __float2half_rn(sigm_f(p1)*tanh_f(cn));
                }
                {
                    float cold = cbuf[(ml+8)*65 + u];
                    float cn = sigm_f(v3)*cold + sigm_f(v2)*tanh_f(p2);
                    cbuf[(ml+8)*65 + u] = cn;
                    hbuf[(ml+8)*66 + u] = __float2half_rn(sigm_f(p3)*tanh_f(cn));
                }
            }
        }
    }
    __syncthreads();
    if (dofc && tid < 256) {                   // fc partial over this CTA's 64 units
        int row = tid >> 1, hf = tid & 1;
        float s = 0.f;
        #pragma unroll
        for (int jj = 0; jj < 32; jj++) {
            int u = hf*32 + jj;
            s += __half2float(hbuf[row*66 + u]) * wfcs[ub + u];
        }
        s += __shfl_xor_sync(0xffffffffu, s, 1);
        if (!hf) fcp[slice*BATCH + m0 + row] = s;
    }
    #pragma unroll
    for (int i = 0; i < 4; i++) {             // c writeback, coalesced
        int idx = tid + i*NTHR;
        int m = idx >> 4, q = idx & 15;
        float4 cv;
        cv.x = cbuf[m*65 + q*4 + 0]; cv.y = cbuf[m*65 + q*4 + 1];
        cv.z = cbuf[m*65 + q*4 + 2]; cv.w = cbuf[m*65 + q*4 + 3];
        *(float4*)&cglob[(size_t)(m0+m)*HID + ub + q*4] = cv;
    }
    const uint32_t* hw = (const uint32_t*)hbuf;
    #pragma unroll
    for (int i = 0; i < 2; i++) {             // h writeback (half), coalesced
        int idx = tid + i*NTHR;
        int m = idx >> 3, q = idx & 7;
        uint4 w;
        int bw = m*33 + q*4;
        w.x = hw[bw]; w.y = hw[bw+1]; w.z = hw[bw+2]; w.w = hw[bw+3];
        *(uint4*)&hout[(size_t)(m0+m)*HID + ub + q*8] = w;
    }
}

// ---------------- tail: last horizon column ----------------
__global__ void fc_tail(const float* __restrict__ fcp, const float* __restrict__ bfc,
                        float* __restrict__ out)
{
    int row = blockIdx.x*128 + threadIdx.x;
    out[(size_t)row*HORIZON + (HORIZON-1)] = bfc[0] + fcp[row] + fcp[BATCH + row];
}

// ---------------- launch ----------------
extern "C" void kernel_launch(void* const* d_in, const int* in_sizes, int n_in,
                              void* d_out, int out_size)
{
    const float* inputs = (const float*)d_in[0];
    const float* Wih0 = (const float*)d_in[1];
    const float* Whh0 = (const float*)d_in[2];
    const float* bih0 = (const float*)d_in[3];
    const float* bhh0 = (const float*)d_in[4];
    const float* Wih1 = (const float*)d_in[5];
    const float* Whh1 = (const float*)d_in[6];
    const float* bih1 = (const float*)d_in[7];
    const float* bhh1 = (const float*)d_in[8];
    const float* Wfc  = (const float*)d_in[9];
    const float* bfc  = (const float*)d_in[10];
    float* out = (float*)d_out;

    __half *pWB0,*pWB1,*ph0,*ph1;
    float *pb0,*pb1,*pc0,*pc1,*pfcp;
    cudaGetSymbolAddress((void**)&pWB0, g_WB0);
    cudaGetSymbolAddress((void**)&pWB1, g_WB1);
    cudaGetSymbolAddress((void**)&pb0 , g_b0 );
    cudaGetSymbolAddress((void**)&pb1 , g_b1 );
    cudaGetSymbolAddress((void**)&ph0 , g_h0 );
    cudaGetSymbolAddress((void**)&ph1 , g_h1 );
    cudaGetSymbolAddress((void**)&pc0 , g_c0 );
    cudaGetSymbolAddress((void**)&pc1 , g_c1 );
    cudaGetSymbolAddress((void**)&pfcp, g_fcp);

    cudaFuncSetAttribute(lstm_cell, cudaFuncAttributeMaxDynamicSharedMemorySize, SMEM_TOTAL);

    prep_kernel<<<2048, 256>>>(Wih0, Whh0, bih0, bhh0, Wih1, Whh1, bih1, bhh1);

    dim3 grid(BATCH/128, 2);
    for (int t = 0; t < TSTEPS; t++) {
        int rp = t & 1, wp = 1 - rp;
        int use_bg = (t > LOOKBACK) ? 1 : 0;
        lstm_cell<<<grid, NTHR, SMEM_TOTAL>>>(
            inputs + t*DIN, TSTEPS*DIN,
            ph0 + rp*STATE, ph0 + rp*STATE,
            pWB0, KROW0, pb0,
            pc0, ph0 + wp*STATE,
            Wfc, bfc, pfcp, out,
            1, use_bg, t - 1 - LOOKBACK, 0);
        lstm_cell<<<grid, NTHR, SMEM_TOTAL>>>(
            nullptr, 0,
            ph0 + wp*STATE, ph1 + rp*STATE,
            pWB1, KROW1, pb1,
            pc1, ph1 + wp*STATE,
            Wfc, bfc, pfcp, out,
            0, 0, 0, (t >= LOOKBACK) ? 1 : 0);
    }
    fc_tail<<<BATCH/128, 128>>>(pfcp, bfc, out);
}

// round 11
// speedup vs baseline: 1.9686x; 1.1638x over previous
#include <cuda_runtime.h>
#include <cuda_fp16.h>
#include <cstdint>

#define BATCH    8192
#define HID      128
#define GATES    512
#define LOOKBACK 48
#define HORIZON  12
#define TSTEPS   60
#define DIN      8
#define STATE    (BATCH*HID)
#define KROW0    160          // 8 x + 24 zero pad + 128 h (halves)
#define KROW1    256
#define NTHR     512

// ---- device globals ----
__device__ __half g_WB0[GATES*KROW0];   // n-major [n][k], n = unit*4+gate
__device__ __half g_WB1[GATES*KROW1];
__device__ float  g_b0 [GATES];
__device__ float  g_b1 [GATES];
__device__ __half g_h0 [2*STATE];
__device__ __half g_h1 [2*STATE];
__device__ float  g_c0 [STATE];
__device__ float  g_c1 [STATE];
__device__ float  g_fcp[2*BATCH];

// ---- smem (bytes): hdr 2048 | A @2048 (<=67584) | B @69632 (<=135168) ----
// epilogue cbuf(128x65 f32)@2048, hbuf(128x66 half)@35328 alias A (dead then).
#define OA     2048
#define OB     69632
#define SM_CB  2048
#define SM_HB  35328
#define SMEM_TOTAL 204800

// ---------------- helpers ----------------
__device__ __forceinline__ uint32_t smem_u32(const void* p){
    uint32_t a;
    asm("{ .reg .u64 t; cvta.to.shared.u64 t, %1; cvt.u32.u64 %0, t; }" : "=r"(a) : "l"(p));
    return a;
}
__device__ __forceinline__ void cpa16(uint32_t dst, const void* src){
    asm volatile("cp.async.cg.shared.global [%0], [%1], 16;" :: "r"(dst), "l"(src));
}
#define CP_COMMIT() asm volatile("cp.async.commit_group;" ::: "memory")
template<int N> __device__ __forceinline__ void cpwait(){
    asm volatile("cp.async.wait_group %0;" :: "n"(N) : "memory");
}
__device__ __forceinline__ void mma16(float* d, const uint32_t* a, const uint32_t* b){
    asm volatile("mma.sync.aligned.m16n8k16.row.col.f32.f16.f16.f32 "
        "{%0,%1,%2,%3}, {%4,%5,%6,%7}, {%8,%9}, {%0,%1,%2,%3};"
        : "+f"(d[0]), "+f"(d[1]), "+f"(d[2]), "+f"(d[3])
        : "r"(a[0]), "r"(a[1]), "r"(a[2]), "r"(a[3]), "r"(b[0]), "r"(b[1]));
}
__device__ __forceinline__ float tanh_f(float x){
    float y; asm("tanh.approx.f32 %0, %1;" : "=f"(y) : "f"(x));
    return y;
}
__device__ __forceinline__ float sigm_f(float x){
    float y; asm("tanh.approx.f32 %0, %1;" : "=f"(y) : "f"(0.5f*x));
    return fmaf(0.5f, y, 0.5f);
}

// ---------------- weight repack (n-major fp16) + state zero ----------------
__global__ void prep_kernel(const float* __restrict__ Wih0, const float* __restrict__ Whh0,
                            const float* __restrict__ bih0, const float* __restrict__ bhh0,
                            const float* __restrict__ Wih1, const float* __restrict__ Whh1,
                            const float* __restrict__ bih1, const float* __restrict__ bhh1)
{
    const int NW0 = GATES*KROW0, NW1 = GATES*KROW1;
    const int total = NW0 + NW1 + 2*GATES + 4*STATE;
    for (int idx = blockIdx.x*blockDim.x + threadIdx.x; idx < total;
         idx += gridDim.x*blockDim.x) {
        int i = idx;
        if (i < NW0) { int n = i/KROW0, k = i%KROW0; int row = (n&3)*HID + (n>>2);
            float v = 0.f;
            if (k < DIN)       v = Wih0[row*DIN + k];
            else if (k >= 32)  v = Whh0[row*HID + (k-32)];
            g_WB0[i] = __float2half_rn(v); continue; }
        i -= NW0;
        if (i < NW1) { int n = i>>8, k = i&255; int row = (n&3)*HID + (n>>2);
            float v = (k < HID) ? Wih1[row*HID + k] : Whh1[row*HID + (k-HID)];
            g_WB1[i] = __float2half_rn(v); continue; }
        i -= NW1;
        if (i < GATES) { int row = (i&3)*HID + (i>>2); g_b0[i] = bih0[row]+bhh0[row]; continue; }
        i -= GATES;
        if (i < GATES) { int row = (i&3)*HID + (i>>2); g_b1[i] = bih1[row]+bhh1[row]; continue; }
        i -= GATES;
        if (i < STATE) { g_h0[i] = __ushort_as_half((unsigned short)0); continue; }
        i -= STATE;
        if (i < STATE) { g_h1[i] = __ushort_as_half((unsigned short)0); continue; }
        i -= STATE;
        if (i < STATE) { g_c0[i] = 0.f; continue; }
        i -= STATE;
        g_c1[i] = 0.f;
    }
}

// ---------------- fused LSTM cell: weights fully smem-resident ----------------
// NCH k-chunks of 32 halves; ASTH/BSTH = A/B row strides in halves.
template<int NCH, int ASTH, int BSTH, bool ISL0>
__global__ __launch_bounds__(NTHR, 1) void lstm_cell(
    const float* __restrict__ xf, int sx,
    const __half* __restrict__ asrc0, const __half* __restrict__ asrc1,
    const __half* __restrict__ WB,
    const float* __restrict__ bias,
    float* __restrict__ cglob, __half* __restrict__ hout,
    const float* __restrict__ Wfc, const float* __restrict__ bfc,
    float* __restrict__ fcp, float* __restrict__ out,
    int use_bg, int outcol, int dofc)
{
    constexpr int KROW = NCH*32;
    extern __shared__ __align__(16) char smem[];
    const int tid = threadIdx.x, lane = tid & 31, wid = tid >> 5;
    const int m0 = blockIdx.x * 128, n0 = blockIdx.y * 256, slice = blockIdx.y;
    const int wm0 = (wid >> 3) * 64, wn0 = (wid & 7) * 32;
    const int g = lane >> 2, tq = lane & 3;
    const uint32_t sbase = smem_u32(smem);
    float* bsm  = (float*)smem;
    float* wfcs = (float*)(smem + 1024);
    float* predS= (float*)(smem + 1536);

    if (tid < 256) bsm[tid] = bias[n0 + tid];
    if (tid < 128) wfcs[tid] = Wfc[tid];

    if (use_bg) {
        if (tid < 128) {
            float pv = bfc[0] + fcp[m0 + tid] + fcp[BATCH + m0 + tid];
            predS[tid] = pv;
            if (n0 == 0) out[(size_t)(m0 + tid)*HORIZON + outcol] = pv;
        }
        __syncthreads();
    }

    // ---- issue ALL chunk loads up-front; one commit group per chunk ----
    {
        const int brow = tid >> 1, bq = tid & 1;        // B: 256 rows, 2 thr/row
        const int arow = tid >> 2, aq = tid & 3;        // A: 128 rows, 4 thr/row
        #pragma unroll
        for (int j = 0; j < NCH; j++) {
            cpa16(sbase + OB + (uint32_t)(brow*(BSTH*2) + j*64 + bq*32),
                  (const char*)WB + ((size_t)(n0+brow)*KROW + j*32)*2 + bq*32);
            cpa16(sbase + OB + (uint32_t)(brow*(BSTH*2) + j*64 + bq*32 + 16),
                  (const char*)WB + ((size_t)(n0+brow)*KROW + j*32)*2 + bq*32 + 16);
            if (!(ISL0 && j == 0)) {
                const __half* ap; int koff;
                if (ISL0)       { ap = asrc0; koff = (j-1)*32; }
                else if (j < 4) { ap = asrc0; koff = j*32; }
                else            { ap = asrc1; koff = (j-4)*32; }
                cpa16(sbase + OA + (uint32_t)(arow*(ASTH*2) + j*64 + aq*16),
                      (const char*)(ap + (size_t)(m0+arow)*HID + koff) + aq*16);
            } else {
                // chunk0 (L0): x cols f32->f16 + BG + zero pad, manual STS
                __half* As0 = (__half*)(smem + OA);
                int m = tid >> 2, part = tid & 3;
                __half hv[8];
                #pragma unroll
                for (int c = 0; c < 8; c++) {
                    int k = part*8 + c;
                    float v = 0.f;
                    if (k < DIN)
                        v = (use_bg && k == 0) ? predS[m] : xf[(size_t)(m0+m)*sx + k];
                    hv[c] = __float2half_rn(v);
                }
                *(uint4*)&As0[m*ASTH + part*8] = *(uint4*)hv;
            }
            CP_COMMIT();
        }
    }

    float acc[4][4][4];
    #pragma unroll
    for (int a = 0; a < 4; a++)
        #pragma unroll
        for (int b = 0; b < 4; b++)
            #pragma unroll
            for (int d = 0; d < 4; d++) acc[a][b][d] = 0.f;

    // ---- mainloop: one wait + one barrier per chunk, no in-loop issue ----
    const uint32_t* As = (const uint32_t*)(smem + OA);
    const uint32_t* Bs = (const uint32_t*)(smem + OB);
    #pragma unroll
    for (int j = 0; j < NCH; j++) {
        switch (NCH - 1 - j) {
            case 0: cpwait<0>(); break;  case 1: cpwait<1>(); break;
            case 2: cpwait<2>(); break;  case 3: cpwait<3>(); break;
            case 4: cpwait<4>(); break;  case 5: cpwait<5>(); break;
            case 6: cpwait<6>(); break;  default: cpwait<7>(); break;
        }
        __syncthreads();
        #pragma unroll
        for (int s = 0; s < 2; s++) {
            uint32_t af[4][4];
            #pragma unroll
            for (int mi = 0; mi < 4; mi++) {
                int r0 = wm0 + mi*16 + g;
                af[mi][0] = As[ r0   *(ASTH/2) + j*16 + s*8 + tq];
                af[mi][1] = As[(r0+8)*(ASTH/2) + j*16 + s*8 + tq];
                af[mi][2] = As[ r0   *(ASTH/2) + j*16 + s*8 + tq + 4];
                af[mi][3] = As[(r0+8)*(ASTH/2) + j*16 + s*8 + tq + 4];
            }
            uint32_t bf[4][2];
            #pragma unroll
            for (int nj = 0; nj < 4; nj++) {
                int nn = wn0 + nj*8 + g;
                bf[nj][0] = Bs[nn*(BSTH/2) + j*16 + s*8 + tq];
                bf[nj][1] = Bs[nn*(BSTH/2) + j*16 + s*8 + tq + 4];
            }
            #pragma unroll
            for (int mi = 0; mi < 4; mi++)
                #pragma unroll
                for (int nj = 0; nj < 4; nj++)
                    mma16(acc[mi][nj], af[mi], bf[nj]);
        }
    }
    __syncthreads();   // all warps done with A before cbuf/hbuf alias it

    // ---- epilogue: all 32 lanes active (even: row r, odd: row r+8) ----
    float*  cbuf = (float*)(smem + SM_CB);
    __half* hbuf = (__half*)(smem + SM_HB);
    const int ub = n0 >> 2;
    #pragma unroll
    for (int i = 0; i < 4; i++) {
        int idx = tid + i*NTHR;
        int m = idx >> 4, q = idx & 15;
        float4 v = *(const float4*)&cglob[(size_t)(m0+m)*HID + ub + q*4];
        cbuf[m*65 + q*4 + 0] = v.x; cbuf[m*65 + q*4 + 1] = v.y;
        cbuf[m*65 + q*4 + 2] = v.z; cbuf[m*65 + q*4 + 3] = v.w;
    }
    __syncthreads();
    const int odd = lane & 1;
    #pragma unroll
    for (int mi = 0; mi < 4; mi++) {
        #pragma unroll
        for (int nj = 0; nj < 4; nj++) {
            int nl = wn0 + nj*8 + 2*tq;
            float v0 = acc[mi][nj][0] + bsm[nl];
            float v1 = acc[mi][nj][1] + bsm[nl+1];
            float v2 = acc[mi][nj][2] + bsm[nl];
            float v3 = acc[mi][nj][3] + bsm[nl+1];
            float x = __shfl_xor_sync(0xffffffffu, odd ? v0 : v2, 1);
            float y = __shfl_xor_sync(0xffffffffu, odd ? v1 : v3, 1);
            // even lane: (i,f)=v0,v1 (row r), (g,o)=x,y ; odd: (i,f)=x,y (row r+8), (g,o)=v2,v3
            float gi = odd ? x  : v0;
            float gf = odd ? y  : v1;
            float gg = odd ? v2 : x;
            float go = odd ? v3 : y;
            int u   = nl >> 2;
            int mlr = wm0 + mi*16 + g + (odd ? 8 : 0);
            float cold = cbuf[mlr*65 + u];
            float cn = sigm_f(gf)*cold + sigm_f(gi)*tanh_f(gg);
            cbuf[mlr*65 + u] = cn;
            hbuf[mlr*66 + u] = __float2half_rn(sigm_f(go)*tanh_f(cn));
        }
    }
    __syncthreads();
    if (dofc && tid < 256) {
        int row = tid >> 1, hf = tid & 1;
        float s = 0.f;
        #pragma unroll
        for (int jj = 0; jj < 32; jj++) {
            int u = hf*32 + jj;
            s += __half2float(hbuf[row*66 + u]) * wfcs[ub + u];
        }
        s += __shfl_xor_sync(0xffffffffu, s, 1);
        if (!hf) fcp[slice*BATCH + m0 + row] = s;
    }
    #pragma unroll
    for (int i = 0; i < 4; i++) {
        int idx = tid + i*NTHR;
        int m = idx >> 4, q = idx & 15;
        float4 cv;
        cv.x = cbuf[m*65 + q*4 + 0]; cv.y = cbuf[m*65 + q*4 + 1];
        cv.z = cbuf[m*65 + q*4 + 2]; cv.w = cbuf[m*65 + q*4 + 3];
        *(float4*)&cglob[(size_t)(m0+m)*HID + ub + q*4] = cv;
    }
    const uint32_t* hw = (const uint32_t*)hbuf;
    #pragma unroll
    for (int i = 0; i < 2; i++) {
        int idx = tid + i*NTHR;
        int m = idx >> 3, q = idx & 7;
        uint4 w;
        int bw = m*33 + q*4;
        w.x = hw[bw]; w.y = hw[bw+1]; w.z = hw[bw+2]; w.w = hw[bw+3];
        *(uint4*)&hout[(size_t)(m0+m)*HID + ub + q*8] = w;
    }
}

// ---------------- tail: last horizon column ----------------
__global__ void fc_tail(const float* __restrict__ fcp, const float* __restrict__ bfc,
                        float* __restrict__ out)
{
    int row = blockIdx.x*128 + threadIdx.x;
    out[(size_t)row*HORIZON + (HORIZON-1)] = bfc[0] + fcp[row] + fcp[BATCH + row];
}

// ---------------- launch ----------------
extern "C" void kernel_launch(void* const* d_in, const int* in_sizes, int n_in,
                              void* d_out, int out_size)
{
    const float* inputs = (const float*)d_in[0];
    const float* Wih0 = (const float*)d_in[1];
    const float* Whh0 = (const float*)d_in[2];
    const float* bih0 = (const float*)d_in[3];
    const float* bhh0 = (const float*)d_in[4];
    const float* Wih1 = (const float*)d_in[5];
    const float* Whh1 = (const float*)d_in[6];
    const float* bih1 = (const float*)d_in[7];
    const float* bhh1 = (const float*)d_in[8];
    const float* Wfc  = (const float*)d_in[9];
    const float* bfc  = (const float*)d_in[10];
    float* out = (float*)d_out;

    __half *pWB0,*pWB1,*ph0,*ph1;
    float *pb0,*pb1,*pc0,*pc1,*pfcp;
    cudaGetSymbolAddress((void**)&pWB0, g_WB0);
    cudaGetSymbolAddress((void**)&pWB1, g_WB1);
    cudaGetSymbolAddress((void**)&pb0 , g_b0 );
    cudaGetSymbolAddress((void**)&pb1 , g_b1 );
    cudaGetSymbolAddress((void**)&ph0 , g_h0 );
    cudaGetSymbolAddress((void**)&ph1 , g_h1 );
    cudaGetSymbolAddress((void**)&pc0 , g_c0 );
    cudaGetSymbolAddress((void**)&pc1 , g_c1 );
    cudaGetSymbolAddress((void**)&pfcp, g_fcp);

    auto k0 = lstm_cell<KROW0/32, KROW0+8, KROW0+8, true >;
    auto k1 = lstm_cell<KROW1/32, KROW1+8, KROW1+8, false>;
    cudaFuncSetAttribute(k0, cudaFuncAttributeMaxDynamicSharedMemorySize, SMEM_TOTAL);
    cudaFuncSetAttribute(k1, cudaFuncAttributeMaxDynamicSharedMemorySize, SMEM_TOTAL);

    prep_kernel<<<2048, 256>>>(Wih0, Whh0, bih0, bhh0, Wih1, Whh1, bih1, bhh1);

    dim3 grid(BATCH/128, 2);
    for (int t = 0; t < TSTEPS; t++) {
        int rp = t & 1, wp = 1 - rp;
        int use_bg = (t > LOOKBACK) ? 1 : 0;
        k0<<<grid, NTHR, SMEM_TOTAL>>>(
            inputs + t*DIN, TSTEPS*DIN,
            ph0 + rp*STATE, ph0 + rp*STATE,
            pWB0, pb0,
            pc0, ph0 + wp*STATE,
            Wfc, bfc, pfcp, out,
            use_bg, t - 1 - LOOKBACK, 0);
        k1<<<grid, NTHR, SMEM_TOTAL>>>(
            nullptr, 0,
            ph0 + wp*STATE, ph1 + rp*STATE,
            pWB1, pb1,
            pc1, ph1 + wp*STATE,
            Wfc, bfc, pfcp, out,
            0, 0, (t >= LOOKBACK) ? 1 : 0);
    }
    fc_tail<<<BATCH/128, 128>>>(pfcp, bfc, out);
}

// round 12
// speedup vs baseline: 2.1175x; 1.0756x over previous
#include <cuda_runtime.h>
#include <cuda_fp16.h>
#include <cstdint>

#define BATCH    8192
#define HID      128
#define GATES    512
#define LOOKBACK 48
#define HORIZON  12
#define TSTEPS   60
#define DIN      8
#define STATE    (BATCH*HID)
#define KROW0    160          // 8 x + 24 zero pad + 128 h (halves)
#define KROW1    256
#define NTHR     512

// ---- device globals ----
__device__ __half g_WB0[GATES*KROW0];   // n-major [n][k], n = unit*4+gate
__device__ __half g_WB1[GATES*KROW1];
__device__ float  g_b0 [GATES];
__device__ float  g_b1 [GATES];
__device__ __half g_h0 [2*STATE];
__device__ __half g_h1 [2*STATE];
__device__ float  g_c0 [STATE];
__device__ float  g_c1 [STATE];
__device__ float  g_fcp[2*BATCH];

// ---- smem (bytes): hdr 2048 | A @2048 (<=67584) | B @69632 (<=135168) ----
#define OA     2048
#define OB     69632
#define SM_CB  2048
#define SM_HB  35328
#define SMEM_TOTAL 204800

// ---------------- helpers ----------------
__device__ __forceinline__ uint32_t smem_u32(const void* p){
    uint32_t a;
    asm("{ .reg .u64 t; cvta.to.shared.u64 t, %1; cvt.u32.u64 %0, t; }" : "=r"(a) : "l"(p));
    return a;
}
__device__ __forceinline__ void cpa16(uint32_t dst, const void* src){
    asm volatile("cp.async.cg.shared.global [%0], [%1], 16;" :: "r"(dst), "l"(src));
}
#define CP_COMMIT() asm volatile("cp.async.commit_group;" ::: "memory")
template<int N> __device__ __forceinline__ void cpwait(){
    asm volatile("cp.async.wait_group %0;" :: "n"(N) : "memory");
}
__device__ __forceinline__ void pdl_wait(){
    asm volatile("griddepcontrol.wait;" ::: "memory");
}
__device__ __forceinline__ void pdl_trigger(){
    asm volatile("griddepcontrol.launch_dependents;");
}
__device__ __forceinline__ void mma16(float* d, const uint32_t* a, const uint32_t* b){
    asm volatile("mma.sync.aligned.m16n8k16.row.col.f32.f16.f16.f32 "
        "{%0,%1,%2,%3}, {%4,%5,%6,%7}, {%8,%9}, {%0,%1,%2,%3};"
        : "+f"(d[0]), "+f"(d[1]), "+f"(d[2]), "+f"(d[3])
        : "r"(a[0]), "r"(a[1]), "r"(a[2]), "r"(a[3]), "r"(b[0]), "r"(b[1]));
}
__device__ __forceinline__ float tanh_f(float x){
    float y; asm("tanh.approx.f32 %0, %1;" : "=f"(y) : "f"(x));
    return y;
}
__device__ __forceinline__ float sigm_f(float x){
    float y; asm("tanh.approx.f32 %0, %1;" : "=f"(y) : "f"(0.5f*x));
    return fmaf(0.5f, y, 0.5f);
}

// ---------------- weight repack (n-major fp16) + state zero ----------------
__global__ void prep_kernel(const float* __restrict__ Wih0, const float* __restrict__ Whh0,
                            const float* __restrict__ bih0, const float* __restrict__ bhh0,
                            const float* __restrict__ Wih1, const float* __restrict__ Whh1,
                            const float* __restrict__ bih1, const float* __restrict__ bhh1)
{
    const int NW0 = GATES*KROW0, NW1 = GATES*KROW1;
    const int total = NW0 + NW1 + 2*GATES + 4*STATE;
    for (int idx = blockIdx.x*blockDim.x + threadIdx.x; idx < total;
         idx += gridDim.x*blockDim.x) {
        int i = idx;
        if (i < NW0) { int n = i/KROW0, k = i%KROW0; int row = (n&3)*HID + (n>>2);
            float v = 0.f;
            if (k < DIN)       v = Wih0[row*DIN + k];
            else if (k >= 32)  v = Whh0[row*HID + (k-32)];
            g_WB0[i] = __float2half_rn(v); continue; }
        i -= NW0;
        if (i < NW1) { int n = i>>8, k = i&255; int row = (n&3)*HID + (n>>2);
            float v = (k < HID) ? Wih1[row*HID + k] : Whh1[row*HID + (k-HID)];
            g_WB1[i] = __float2half_rn(v); continue; }
        i -= NW1;
        if (i < GATES) { int row = (i&3)*HID + (i>>2); g_b0[i] = bih0[row]+bhh0[row]; continue; }
        i -= GATES;
        if (i < GATES) { int row = (i&3)*HID + (i>>2); g_b1[i] = bih1[row]+bhh1[row]; continue; }
        i -= GATES;
        if (i < STATE) { g_h0[i] = __ushort_as_half((unsigned short)0); continue; }
        i -= STATE;
        if (i < STATE) { g_h1[i] = __ushort_as_half((unsigned short)0); continue; }
        i -= STATE;
        if (i < STATE) { g_c0[i] = 0.f; continue; }
        i -= STATE;
        g_c1[i] = 0.f;
    }
}

// ---------------- fused LSTM cell: smem-resident weights + PDL overlap ----------------
template<int NCH, int ASTH, int BSTH, bool ISL0>
__global__ __launch_bounds__(NTHR, 1) void lstm_cell(
    const float* __restrict__ xf, int sx,
    const __half* __restrict__ asrc0, const __half* __restrict__ asrc1,
    const __half* __restrict__ WB,
    const float* __restrict__ bias,
    float* __restrict__ cglob, __half* __restrict__ hout,
    const float* __restrict__ Wfc, const float* __restrict__ bfc,
    float* __restrict__ fcp, float* __restrict__ out,
    int use_bg, int outcol, int dofc)
{
    constexpr int KROW = NCH*32;
    extern __shared__ __align__(16) char smem[];
    const int tid = threadIdx.x, lane = tid & 31, wid = tid >> 5;
    const int m0 = blockIdx.x * 128, n0 = blockIdx.y * 256, slice = blockIdx.y;
    const int wm0 = (wid >> 3) * 64, wn0 = (wid & 7) * 32;
    const int g = lane >> 2, tq = lane & 3;
    const uint32_t sbase = smem_u32(smem);
    float* bsm  = (float*)smem;
    float* wfcs = (float*)(smem + 1024);
    float* predS= (float*)(smem + 1536);

    // ---- PDL phase 1: weight loads (independent of predecessor) ----
    {
        const int brow = tid >> 1, bq = tid & 1;        // B: 256 rows, 2 thr/row
        #pragma unroll
        for (int j = 0; j < NCH; j++) {
            cpa16(sbase + OB + (uint32_t)(brow*(BSTH*2) + j*64 + bq*32),
                  (const char*)WB + ((size_t)(n0+brow)*KROW + j*32)*2 + bq*32);
            cpa16(sbase + OB + (uint32_t)(brow*(BSTH*2) + j*64 + bq*32 + 16),
                  (const char*)WB + ((size_t)(n0+brow)*KROW + j*32)*2 + bq*32 + 16);
            CP_COMMIT();
        }
    }

    // ---- PDL phase 2: wait for predecessor's memory, then dependent loads ----
    pdl_wait();

    if (tid < 256) bsm[tid] = bias[n0 + tid];
    if (tid < 128) wfcs[tid] = Wfc[tid];
    if (use_bg) {
        if (tid < 128) {
            float pv = bfc[0] + fcp[m0 + tid] + fcp[BATCH + m0 + tid];
            predS[tid] = pv;
            if (n0 == 0) out[(size_t)(m0 + tid)*HORIZON + outcol] = pv;
        }
        __syncthreads();
    }

    {
        const int arow = tid >> 2, aq = tid & 3;        // A: 128 rows, 4 thr/row
        #pragma unroll
        for (int j = 0; j < NCH; j++) {
            if (!(ISL0 && j == 0)) {
                const __half* ap; int koff;
                if (ISL0)       { ap = asrc0; koff = (j-1)*32; }
                else if (j < 4) { ap = asrc0; koff = j*32; }
                else            { ap = asrc1; koff = (j-4)*32; }
                cpa16(sbase + OA + (uint32_t)(arow*(ASTH*2) + j*64 + aq*16),
                      (const char*)(ap + (size_t)(m0+arow)*HID + koff) + aq*16);
            } else {
                // chunk0 (L0): x cols f32->f16 + BG + zero pad, manual STS
                __half* As0 = (__half*)(smem + OA);
                int m = tid >> 2, part = tid & 3;
                __half hv[8];
                #pragma unroll
                for (int c = 0; c < 8; c++) {
                    int k = part*8 + c;
                    float v = 0.f;
                    if (k < DIN)
                        v = (use_bg && k == 0) ? predS[m] : xf[(size_t)(m0+m)*sx + k];
                    hv[c] = __float2half_rn(v);
                }
                *(uint4*)&As0[m*ASTH + part*8] = *(uint4*)hv;
            }
            CP_COMMIT();
        }
    }

    float acc[4][4][4];
    #pragma unroll
    for (int a = 0; a < 4; a++)
        #pragma unroll
        for (int b = 0; b < 4; b++)
            #pragma unroll
            for (int d = 0; d < 4; d++) acc[a][b][d] = 0.f;

    // ---- mainloop: groups = [B0..B_{NCH-1}, A0..A_{NCH-1}];
    //      outstanding <= NCH-1-j  =>  all B + A0..Aj complete ----
    const uint32_t* As = (const uint32_t*)(smem + OA);
    const uint32_t* Bs = (const uint32_t*)(smem + OB);
    #pragma unroll
    for (int j = 0; j < NCH; j++) {
        switch (NCH - 1 - j) {
            case 0: cpwait<0>(); break;  case 1: cpwait<1>(); break;
            case 2: cpwait<2>(); break;  case 3: cpwait<3>(); break;
            case 4: cpwait<4>(); break;  case 5: cpwait<5>(); break;
            case 6: cpwait<6>(); break;  default: cpwait<7>(); break;
        }
        __syncthreads();
        #pragma unroll
        for (int s = 0; s < 2; s++) {
            uint32_t af[4][4];
            #pragma unroll
            for (int mi = 0; mi < 4; mi++) {
                int r0 = wm0 + mi*16 + g;
                af[mi][0] = As[ r0   *(ASTH/2) + j*16 + s*8 + tq];
                af[mi][1] = As[(r0+8)*(ASTH/2) + j*16 + s*8 + tq];
                af[mi][2] = As[ r0   *(ASTH/2) + j*16 + s*8 + tq + 4];
                af[mi][3] = As[(r0+8)*(ASTH/2) + j*16 + s*8 + tq + 4];
            }
            uint32_t bf[4][2];
            #pragma unroll
            for (int nj = 0; nj < 4; nj++) {
                int nn = wn0 + nj*8 + g;
                bf[nj][0] = Bs[nn*(BSTH/2) + j*16 + s*8 + tq];
                bf[nj][1] = Bs[nn*(BSTH/2) + j*16 + s*8 + tq + 4];
            }
            #pragma unroll
            for (int mi = 0; mi < 4; mi++)
                #pragma unroll
                for (int nj = 0; nj < 4; nj++)
                    mma16(acc[mi][nj], af[mi], bf[nj]);
        }
    }
    __syncthreads();   // all warps done with A before cbuf/hbuf alias it

    // ---- epilogue: all 32 lanes active (even: row r, odd: row r+8) ----
    float*  cbuf = (float*)(smem + SM_CB);
    __half* hbuf = (__half*)(smem + SM_HB);
    const int ub = n0 >> 2;
    #pragma unroll
    for (int i = 0; i < 4; i++) {
        int idx = tid + i*NTHR;
        int m = idx >> 4, q = idx & 15;
        float4 v = *(const float4*)&cglob[(size_t)(m0+m)*HID + ub + q*4];
        cbuf[m*65 + q*4 + 0] = v.x; cbuf[m*65 + q*4 + 1] = v.y;
        cbuf[m*65 + q*4 + 2] = v.z; cbuf[m*65 + q*4 + 3] = v.w;
    }
    __syncthreads();
    const int odd = lane & 1;
    #pragma unroll
    for (int mi = 0; mi < 4; mi++) {
        #pragma unroll
        for (int nj = 0; nj < 4; nj++) {
            int nl = wn0 + nj*8 + 2*tq;
            float v0 = acc[mi][nj][0] + bsm[nl];
            float v1 = acc[mi][nj][1] + bsm[nl+1];
            float v2 = acc[mi][nj][2] + bsm[nl];
            float v3 = acc[mi][nj][3] + bsm[nl+1];
            float x = __shfl_xor_sync(0xffffffffu, odd ? v0 : v2, 1);
            float y = __shfl_xor_sync(0xffffffffu, odd ? v1 : v3, 1);
            float gi = odd ? x  : v0;
            float gf = odd ? y  : v1;
            float gg = odd ? v2 : x;
            float go = odd ? v3 : y;
            int u   = nl >> 2;
            int mlr = wm0 + mi*16 + g + (odd ? 8 : 0);
            float cold = cbuf[mlr*65 + u];
            float cn = sigm_f(gf)*cold + sigm_f(gi)*tanh_f(gg);
            cbuf[mlr*65 + u] = cn;
            hbuf[mlr*66 + u] = __float2half_rn(sigm_f(go)*tanh_f(cn));
        }
    }
    __syncthreads();
    if (dofc && tid < 256) {
        int row = tid >> 1, hf = tid & 1;
        float s = 0.f;
        #pragma unroll
        for (int jj = 0; jj < 32; jj++) {
            int u = hf*32 + jj;
            s += __half2float(hbuf[row*66 + u]) * wfcs[ub + u];
        }
        s += __shfl_xor_sync(0xffffffffu, s, 1);
        if (!hf) fcp[slice*BATCH + m0 + row] = s;
    }
    #pragma unroll
    for (int i = 0; i < 4; i++) {
        int idx = tid + i*NTHR;
        int m = idx >> 4, q = idx & 15;
        float4 cv;
        cv.x = cbuf[m*65 + q*4 + 0]; cv.y = cbuf[m*65 + q*4 + 1];
        cv.z = cbuf[m*65 + q*4 + 2]; cv.w = cbuf[m*65 + q*4 + 3];
        *(float4*)&cglob[(size_t)(m0+m)*HID + ub + q*4] = cv;
    }
    const uint32_t* hw = (const uint32_t*)hbuf;
    #pragma unroll
    for (int i = 0; i < 2; i++) {
        int idx = tid + i*NTHR;
        int m = idx >> 3, q = idx & 7;
        uint4 w;
        int bw = m*33 + q*4;
        w.x = hw[bw]; w.y = hw[bw+1]; w.z = hw[bw+2]; w.w = hw[bw+3];
        *(uint4*)&hout[(size_t)(m0+m)*HID + ub + q*8] = w;
    }
    // ---- PDL phase 3: allow the next kernel to begin its weight loads ----
    pdl_trigger();
}

// ---------------- tail: last horizon column ----------------
__global__ void fc_tail(const float* __restrict__ fcp, const float* __restrict__ bfc,
                        float* __restrict__ out)
{
    int row = blockIdx.x*128 + threadIdx.x;
    out[(size_t)row*HORIZON + (HORIZON-1)] = bfc[0] + fcp[row] + fcp[BATCH + row];
}

// ---------------- launch ----------------
extern "C" void kernel_launch(void* const* d_in, const int* in_sizes, int n_in,
                              void* d_out, int out_size)
{
    const float* inputs = (const float*)d_in[0];
    const float* Wih0 = (const float*)d_in[1];
    const float* Whh0 = (const float*)d_in[2];
    const float* bih0 = (const float*)d_in[3];
    const float* bhh0 = (const float*)d_in[4];
    const float* Wih1 = (const float*)d_in[5];
    const float* Whh1 = (const float*)d_in[6];
    const float* bih1 = (const float*)d_in[7];
    const float* bhh1 = (const float*)d_in[8];
    const float* Wfc  = (const float*)d_in[9];
    const float* bfc  = (const float*)d_in[10];
    float* out = (float*)d_out;

    __half *pWB0,*pWB1,*ph0,*ph1;
    float *pb0,*pb1,*pc0,*pc1,*pfcp;
    cudaGetSymbolAddress((void**)&pWB0, g_WB0);
    cudaGetSymbolAddress((void**)&pWB1, g_WB1);
    cudaGetSymbolAddress((void**)&pb0 , g_b0 );
    cudaGetSymbolAddress((void**)&pb1 , g_b1 );
    cudaGetSymbolAddress((void**)&ph0 , g_h0 );
    cudaGetSymbolAddress((void**)&ph1 , g_h1 );
    cudaGetSymbolAddress((void**)&pc0 , g_c0 );
    cudaGetSymbolAddress((void**)&pc1 , g_c1 );
    cudaGetSymbolAddress((void**)&pfcp, g_fcp);

    auto k0 = lstm_cell<KROW0/32, KROW0+8, KROW0+8, true >;
    auto k1 = lstm_cell<KROW1/32, KROW1+8, KROW1+8, false>;
    cudaFuncSetAttribute(k0, cudaFuncAttributeMaxDynamicSharedMemorySize, SMEM_TOTAL);
    cudaFuncSetAttribute(k1, cudaFuncAttributeMaxDynamicSharedMemorySize, SMEM_TOTAL);

    prep_kernel<<<2048, 256>>>(Wih0, Whh0, bih0, bhh0, Wih1, Whh1, bih1, bhh1);

    dim3 grid(BATCH/128, 2);
    cudaLaunchConfig_t cfg = {};
    cfg.gridDim = grid;
    cfg.blockDim = dim3(NTHR, 1, 1);
    cfg.dynamicSmemBytes = SMEM_TOTAL;
    cfg.stream = 0;
    cudaLaunchAttribute attrs[1];
    attrs[0].id = cudaLaunchAttributeProgrammaticStreamSerialization;
    attrs[0].val.programmaticStreamSerializationAllowed = 1;
    cfg.attrs = attrs;
    cfg.numAttrs = 1;

    for (int t = 0; t < TSTEPS; t++) {
        int rp = t & 1, wp = 1 - rp;
        int use_bg = (t > LOOKBACK) ? 1 : 0;
        cudaLaunchKernelEx(&cfg, k0,
            (const float*)(inputs + t*DIN), (int)(TSTEPS*DIN),
            (const __half*)(ph0 + rp*STATE), (const __half*)(ph0 + rp*STATE),
            (const __half*)pWB0, (const float*)pb0,
            pc0, (__half*)(ph0 + wp*STATE),
            Wfc, bfc, pfcp, out,
            use_bg, t - 1 - LOOKBACK, 0);
        cudaLaunchKernelEx(&cfg, k1,
            (const float*)nullptr, 0,
            (const __half*)(ph0 + wp*STATE), (const __half*)(ph1 + rp*STATE),
            (const __half*)pWB1, (const float*)pb1,
            pc1, (__half*)(ph1 + wp*STATE),
            Wfc, bfc, pfcp, out,
            0, 0, (t >= LOOKBACK) ? 1 : 0);
    }
    fc_tail<<<BATCH/128, 128>>>(pfcp, bfc, out);
}

// round 13
// speedup vs baseline: 2.1350x; 1.0083x over previous
#include <cuda_runtime.h>
#include <cuda_fp16.h>
#include <cstdint>

#define BATCH    8192
#define HID      128
#define GATES    512
#define LOOKBACK 48
#define HORIZON  12
#define TSTEPS   60
#define DIN      8
#define STATE    (BATCH*HID)
#define KROW0    160          // 8 x + 24 zero pad + 128 h (halves)
#define KROW1    256
#define NTHR     512

// ---- device globals ----
__device__ __half g_WB0[GATES*KROW0];   // n-major [n][k], n = unit*4+gate
__device__ __half g_WB1[GATES*KROW1];
__device__ float  g_b0 [GATES];
__device__ float  g_b1 [GATES];
__device__ __half g_h0 [2*STATE];
__device__ __half g_h1 [2*STATE];
__device__ float  g_c0 [STATE];
__device__ float  g_c1 [STATE];
__device__ float  g_fcp[2*BATCH];

// ---- smem (bytes): hdr 2048 | A @2048 (<=67584) | B @69632 (<=135168) ----
#define OA     2048
#define OB     69632
#define SM_CB  2048
#define SM_HB  35328
#define SMEM_TOTAL 204800

// ---------------- helpers ----------------
__device__ __forceinline__ uint32_t smem_u32(const void* p){
    uint32_t a;
    asm("{ .reg .u64 t; cvta.to.shared.u64 t, %1; cvt.u32.u64 %0, t; }" : "=r"(a) : "l"(p));
    return a;
}
__device__ __forceinline__ void cpa16(uint32_t dst, const void* src){
    asm volatile("cp.async.cg.shared.global [%0], [%1], 16;" :: "r"(dst), "l"(src));
}
#define CP_COMMIT() asm volatile("cp.async.commit_group;" ::: "memory")
#define CP_WAIT0()  asm volatile("cp.async.wait_group 0;" ::: "memory")
__device__ __forceinline__ void pdl_wait(){
    asm volatile("griddepcontrol.wait;" ::: "memory");
}
__device__ __forceinline__ void pdl_trigger(){
    asm volatile("griddepcontrol.launch_dependents;");
}
__device__ __forceinline__ void mma16(float* d, const uint32_t* a, const uint32_t* b){
    asm volatile("mma.sync.aligned.m16n8k16.row.col.f32.f16.f16.f32 "
        "{%0,%1,%2,%3}, {%4,%5,%6,%7}, {%8,%9}, {%0,%1,%2,%3};"
        : "+f"(d[0]), "+f"(d[1]), "+f"(d[2]), "+f"(d[3])
        : "r"(a[0]), "r"(a[1]), "r"(a[2]), "r"(a[3]), "r"(b[0]), "r"(b[1]));
}
__device__ __forceinline__ float tanh_f(float x){
    float y; asm("tanh.approx.f32 %0, %1;" : "=f"(y) : "f"(x));
    return y;
}
__device__ __forceinline__ float sigm_f(float x){
    float y; asm("tanh.approx.f32 %0, %1;" : "=f"(y) : "f"(0.5f*x));
    return fmaf(0.5f, y, 0.5f);
}

// ---------------- weight repack (n-major fp16) + state zero ----------------
__global__ void prep_kernel(const float* __restrict__ Wih0, const float* __restrict__ Whh0,
                            const float* __restrict__ bih0, const float* __restrict__ bhh0,
                            const float* __restrict__ Wih1, const float* __restrict__ Whh1,
                            const float* __restrict__ bih1, const float* __restrict__ bhh1)
{
    const int NW0 = GATES*KROW0, NW1 = GATES*KROW1;
    const int total = NW0 + NW1 + 2*GATES + 4*STATE;
    for (int idx = blockIdx.x*blockDim.x + threadIdx.x; idx < total;
         idx += gridDim.x*blockDim.x) {
        int i = idx;
        if (i < NW0) { int n = i/KROW0, k = i%KROW0; int row = (n&3)*HID + (n>>2);
            float v = 0.f;
            if (k < DIN)       v = Wih0[row*DIN + k];
            else if (k >= 32)  v = Whh0[row*HID + (k-32)];
            g_WB0[i] = __float2half_rn(v); continue; }
        i -= NW0;
        if (i < NW1) { int n = i>>8, k = i&255; int row = (n&3)*HID + (n>>2);
            float v = (k < HID) ? Wih1[row*HID + k] : Whh1[row*HID + (k-HID)];
            g_WB1[i] = __float2half_rn(v); continue; }
        i -= NW1;
        if (i < GATES) { int row = (i&3)*HID + (i>>2); g_b0[i] = bih0[row]+bhh0[row]; continue; }
        i -= GATES;
        if (i < GATES) { int row = (i&3)*HID + (i>>2); g_b1[i] = bih1[row]+bhh1[row]; continue; }
        i -= GATES;
        if (i < STATE) { g_h0[i] = __ushort_as_half((unsigned short)0); continue; }
        i -= STATE;
        if (i < STATE) { g_h1[i] = __ushort_as_half((unsigned short)0); continue; }
        i -= STATE;
        if (i < STATE) { g_c0[i] = 0.f; continue; }
        i -= STATE;
        g_c1[i] = 0.f;
    }
}

// ---------------- fused LSTM cell: PDL with maximal pre-wait prefetch ----------------
// Dependency depth: only h0 (for L1) / pred (for L0-decode) come from the
// IMMEDIATE predecessor. B weights, h_prev of the same layer, c state, bias,
// wfc all come from >=2 launches back -> issued BEFORE griddepcontrol.wait.
template<int NCH, int ASTH, int BSTH, bool ISL0>
__global__ __launch_bounds__(NTHR, 1) void lstm_cell(
    const float* __restrict__ xf, int sx,
    const __half* __restrict__ asrc0, const __half* __restrict__ asrc1,
    const __half* __restrict__ WB,
    const float* __restrict__ bias,
    float* __restrict__ cglob, __half* __restrict__ hout,
    const float* __restrict__ Wfc, const float* __restrict__ bfc,
    float* __restrict__ fcp, float* __restrict__ out,
    int use_bg, int outcol, int dofc)
{
    constexpr int KROW = NCH*32;
    extern __shared__ __align__(16) char smem[];
    const int tid = threadIdx.x, lane = tid & 31, wid = tid >> 5;
    const int m0 = blockIdx.x * 128, n0 = blockIdx.y * 256, slice = blockIdx.y;
    const int wm0 = (wid >> 3) * 64, wn0 = (wid & 7) * 32;
    const int g = lane >> 2, tq = lane & 3;
    const uint32_t sbase = smem_u32(smem);
    float* bsm  = (float*)smem;
    float* wfcs = (float*)(smem + 1024);
    float* predS= (float*)(smem + 1536);

    // ======== PRE-WAIT: everything with dependency depth >= 2 ========
    {
        const int brow = tid >> 1, bq = tid & 1;        // B: 256 rows, 2 thr/row
        #pragma unroll
        for (int j = 0; j < NCH; j++) {
            cpa16(sbase + OB + (uint32_t)(brow*(BSTH*2) + j*64 + bq*32),
                  (const char*)WB + ((size_t)(n0+brow)*KROW + j*32)*2 + bq*32);
            cpa16(sbase + OB + (uint32_t)(brow*(BSTH*2) + j*64 + bq*32 + 16),
                  (const char*)WB + ((size_t)(n0+brow)*KROW + j*32)*2 + bq*32 + 16);
        }
        const int arow = tid >> 2, aq = tid & 3;        // A: 128 rows, 4 thr/row
        if (ISL0) {
            #pragma unroll
            for (int j = 1; j < NCH; j++)               // h0_prev: 2 launches back
                cpa16(sbase + OA + (uint32_t)(arow*(ASTH*2) + j*64 + aq*16),
                      (const char*)(asrc0 + (size_t)(m0+arow)*HID + (j-1)*32) + aq*16);
        } else {
            #pragma unroll
            for (int j = 4; j < 8; j++)                 // h1_prev: 2 launches back
                cpa16(sbase + OA + (uint32_t)(arow*(ASTH*2) + j*64 + aq*16),
                      (const char*)(asrc1 + (size_t)(m0+arow)*HID + (j-4)*32) + aq*16);
        }
    }
    if (tid < 256) bsm[tid] = bias[n0 + tid];           // static
    if (tid < 128) wfcs[tid] = Wfc[tid];                // static

    // ======== WAIT on immediate predecessor, then dependent loads ========
    pdl_wait();

    if (ISL0) {
        if (use_bg) {
            if (tid < 128) {
                float pv = bfc[0] + fcp[m0 + tid] + fcp[BATCH + m0 + tid];
                predS[tid] = pv;
                if (n0 == 0) out[(size_t)(m0 + tid)*HORIZON + outcol] = pv;
            }
            __syncthreads();    // predS visible to chunk0 writers
        }
        // chunk0: x cols f32->f16 (+BG) + zero pad, manual STS
        __half* As0 = (__half*)(smem + OA);
        int m = tid >> 2, part = tid & 3;
        __half hv[8];
        #pragma unroll
        for (int c = 0; c < 8; c++) {
            int k = part*8 + c;
            float v = 0.f;
            if (k < DIN)
                v = (use_bg && k == 0) ? predS[m] : xf[(size_t)(m0+m)*sx + k];
            hv[c] = __float2half_rn(v);
        }
        *(uint4*)&As0[m*ASTH + part*8] = *(uint4*)hv;
    } else {
        const int arow = tid >> 2, aq = tid & 3;
        #pragma unroll
        for (int j = 0; j < 4; j++)                     // h0 current: immediate dep
            cpa16(sbase + OA + (uint32_t)(arow*(ASTH*2) + j*64 + aq*16),
                  (const char*)(asrc0 + (size_t)(m0+arow)*HID + j*32) + aq*16);
    }
    CP_COMMIT();

    float acc[4][4][4];
    #pragma unroll
    for (int a = 0; a < 4; a++)
        #pragma unroll
        for (int b = 0; b < 4; b++)
            #pragma unroll
            for (int d = 0; d < 4; d++) acc[a][b][d] = 0.f;

    // ======== single wait + single barrier, then uninterrupted mma ========
    CP_WAIT0();
    __syncthreads();
    const uint32_t* As = (const uint32_t*)(smem + OA);
    const uint32_t* Bs = (const uint32_t*)(smem + OB);
    #pragma unroll
    for (int j = 0; j < NCH; j++) {
        #pragma unroll
        for (int s = 0; s < 2; s++) {
            uint32_t af[4][4];
            #pragma unroll
            for (int mi = 0; mi < 4; mi++) {
                int r0 = wm0 + mi*16 + g;
                af[mi][0] = As[ r0   *(ASTH/2) + j*16 + s*8 + tq];
                af[mi][1] = As[(r0+8)*(ASTH/2) + j*16 + s*8 + tq];
                af[mi][2] = As[ r0   *(ASTH/2) + j*16 + s*8 + tq + 4];
                af[mi][3] = As[(r0+8)*(ASTH/2) + j*16 + s*8 + tq + 4];
            }
            uint32_t bf[4][2];
            #pragma unroll
            for (int nj = 0; nj < 4; nj++) {
                int nn = wn0 + nj*8 + g;
                bf[nj][0] = Bs[nn*(BSTH/2) + j*16 + s*8 + tq];
                bf[nj][1] = Bs[nn*(BSTH/2) + j*16 + s*8 + tq + 4];
            }
            #pragma unroll
            for (int mi = 0; mi < 4; mi++)
                #pragma unroll
                for (int nj = 0; nj < 4; nj++)
                    mma16(acc[mi][nj], af[mi], bf[nj]);
        }
    }
    __syncthreads();   // all warps done with A before cbuf/hbuf alias it

    // ======== epilogue: all 32 lanes active ========
    float*  cbuf = (float*)(smem + SM_CB);
    __half* hbuf = (__half*)(smem + SM_HB);
    const int ub = n0 >> 2;
    #pragma unroll
    for (int i = 0; i < 4; i++) {
        int idx = tid + i*NTHR;
        int m = idx >> 4, q = idx & 15;
        float4 v = *(const float4*)&cglob[(size_t)(m0+m)*HID + ub + q*4];
        cbuf[m*65 + q*4 + 0] = v.x; cbuf[m*65 + q*4 + 1] = v.y;
        cbuf[m*65 + q*4 + 2] = v.z; cbuf[m*65 + q*4 + 3] = v.w;
    }
    __syncthreads();
    const int odd = lane & 1;
    #pragma unroll
    for (int mi = 0; mi < 4; mi++) {
        #pragma unroll
        for (int nj = 0; nj < 4; nj++) {
            int nl = wn0 + nj*8 + 2*tq;
            float v0 = acc[mi][nj][0] + bsm[nl];
            float v1 = acc[mi][nj][1] + bsm[nl+1];
            float v2 = acc[mi][nj][2] + bsm[nl];
            float v3 = acc[mi][nj][3] + bsm[nl+1];
            float x = __shfl_xor_sync(0xffffffffu, odd ? v0 : v2, 1);
            float y = __shfl_xor_sync(0xffffffffu, odd ? v1 : v3, 1);
            float gi = odd ? x  : v0;
            float gf = odd ? y  : v1;
            float gg = odd ? v2 : x;
            float go = odd ? v3 : y;
            int u   = nl >> 2;
            int mlr = wm0 + mi*16 + g + (odd ? 8 : 0);
            float cold = cbuf[mlr*65 + u];
            float cn = sigm_f(gf)*cold + sigm_f(gi)*tanh_f(gg);
            cbuf[mlr*65 + u] = cn;
            hbuf[mlr*66 + u] = __float2half_rn(sigm_f(go)*tanh_f(cn));
        }
    }
    __syncthreads();
    if (dofc && tid < 256) {
        int row = tid >> 1, hf = tid & 1;
        float s = 0.f;
        #pragma unroll
        for (int jj = 0; jj < 32; jj++) {
            int u = hf*32 + jj;
            s += __half2float(hbuf[row*66 + u]) * wfcs[ub + u];
        }
        s += __shfl_xor_sync(0xffffffffu, s, 1);
        if (!hf) fcp[slice*BATCH + m0 + row] = s;
    }
    #pragma unroll
    for (int i = 0; i < 4; i++) {
        int idx = tid + i*NTHR;
        int m = idx >> 4, q = idx & 15;
        float4 cv;
        cv.x = cbuf[m*65 + q*4 + 0]; cv.y = cbuf[m*65 + q*4 + 1];
        cv.z = cbuf[m*65 + q*4 + 2]; cv.w = cbuf[m*65 + q*4 + 3];
        *(float4*)&cglob[(size_t)(m0+m)*HID + ub + q*4] = cv;
    }
    const uint32_t* hw = (const uint32_t*)hbuf;
    #pragma unroll
    for (int i = 0; i < 2; i++) {
        int idx = tid + i*NTHR;
        int m = idx >> 3, q = idx & 7;
        uint4 w;
        int bw = m*33 + q*4;
        w.x = hw[bw]; w.y = hw[bw+1]; w.z = hw[bw+2]; w.w = hw[bw+3];
        *(uint4*)&hout[(size_t)(m0+m)*HID + ub + q*8] = w;
    }
    pdl_trigger();
}

// ---------------- tail: last horizon column ----------------
__global__ void fc_tail(const float* __restrict__ fcp, const float* __restrict__ bfc,
                        float* __restrict__ out)
{
    int row = blockIdx.x*128 + threadIdx.x;
    out[(size_t)row*HORIZON + (HORIZON-1)] = bfc[0] + fcp[row] + fcp[BATCH + row];
}

// ---------------- launch ----------------
extern "C" void kernel_launch(void* const* d_in, const int* in_sizes, int n_in,
                              void* d_out, int out_size)
{
    const float* inputs = (const float*)d_in[0];
    const float* Wih0 = (const float*)d_in[1];
    const float* Whh0 = (const float*)d_in[2];
    const float* bih0 = (const float*)d_in[3];
    const float* bhh0 = (const float*)d_in[4];
    const float* Wih1 = (const float*)d_in[5];
    const float* Whh1 = (const float*)d_in[6];
    const float* bih1 = (const float*)d_in[7];
    const float* bhh1 = (const float*)d_in[8];
    const float* Wfc  = (const float*)d_in[9];
    const float* bfc  = (const float*)d_in[10];
    float* out = (float*)d_out;

    __half *pWB0,*pWB1,*ph0,*ph1;
    float *pb0,*pb1,*pc0,*pc1,*pfcp;
    cudaGetSymbolAddress((void**)&pWB0, g_WB0);
    cudaGetSymbolAddress((void**)&pWB1, g_WB1);
    cudaGetSymbolAddress((void**)&pb0 , g_b0 );
    cudaGetSymbolAddress((void**)&pb1 , g_b1 );
    cudaGetSymbolAddress((void**)&ph0 , g_h0 );
    cudaGetSymbolAddress((void**)&ph1 , g_h1 );
    cudaGetSymbolAddress((void**)&pc0 , g_c0 );
    cudaGetSymbolAddress((void**)&pc1 , g_c1 );
    cudaGetSymbolAddress((void**)&pfcp, g_fcp);

    auto k0 = lstm_cell<KROW0/32, KROW0+8, KROW0+8, true >;
    auto k1 = lstm_cell<KROW1/32, KROW1+8, KROW1+8, false>;
    cudaFuncSetAttribute(k0, cudaFuncAttributeMaxDynamicSharedMemorySize, SMEM_TOTAL);
    cudaFuncSetAttribute(k1, cudaFuncAttributeMaxDynamicSharedMemorySize, SMEM_TOTAL);

    prep_kernel<<<2048, 256>>>(Wih0, Whh0, bih0, bhh0, Wih1, Whh1, bih1, bhh1);

    dim3 grid(BATCH/128, 2);
    cudaLaunchConfig_t cfg = {};
    cfg.gridDim = grid;
    cfg.blockDim = dim3(NTHR, 1, 1);
    cfg.dynamicSmemBytes = SMEM_TOTAL;
    cfg.stream = 0;
    cudaLaunchAttribute attrs[1];
    attrs[0].id = cudaLaunchAttributeProgrammaticStreamSerialization;
    attrs[0].val.programmaticStreamSerializationAllowed = 1;
    cfg.attrs = attrs;
    cfg.numAttrs = 1;

    for (int t = 0; t < TSTEPS; t++) {
        int rp = t & 1, wp = 1 - rp;
        int use_bg = (t > LOOKBACK) ? 1 : 0;
        cudaLaunchKernelEx(&cfg, k0,
            (const float*)(inputs + t*DIN), (int)(TSTEPS*DIN),
            (const __half*)(ph0 + rp*STATE), (const __half*)(ph0 + rp*STATE),
            (const __half*)pWB0, (const float*)pb0,
            pc0, (__half*)(ph0 + wp*STATE),
            Wfc, bfc, pfcp, out,
            use_bg, t - 1 - LOOKBACK, 0);
        cudaLaunchKernelEx(&cfg, k1,
            (const float*)nullptr, 0,
            (const __half*)(ph0 + wp*STATE), (const __half*)(ph1 + rp*STATE),
            (const __half*)pWB1, (const float*)pb1,
            pc1, (__half*)(ph1 + wp*STATE),
            Wfc, bfc, pfcp, out,
            0, 0, (t >= LOOKBACK) ? 1 : 0);
    }
    fc_tail<<<BATCH/128, 128>>>(pfcp, bfc, out);
}